// round 16
// baseline (speedup 1.0000x reference)
#include <cuda_runtime.h>
#include <cuda_bf16.h>

// SimplePatchScorer: x (512,3,224,224) f32, W (1,768) f32, b (1,) f32
// out (512,196) f32.
//
// f = t*588 + e; t = i*16 + j; e = band*14 + wn (42 bands of 896 float4).
// row = f/768, k = f mod 768.
//
// R16 (base = R14, 54.0us, loop identical + L2 prefetch):
//  (1) CTA = (image, ihalf) rows ihalf*98..+97 (128*588 = 98*768), 1024
//      CTAs x 128 thr, occ 7, ~99% wave balance (R14-proven).
//  (2) prefetch.global.L2 2 bands (28 iters) ahead each iteration: adds
//      DRAM->L2 concurrency with ZERO register cost, so the RF-limited
//      7-deep demand batch covers L2 latency (~250cyc) instead of DRAM
//      (~600cyc). The band-periodic layout makes the lookahead address
//      off + 2*896, same wn - no extra address state.
//  (3) LDG.128 + __ldcs, doubled swizzled weights, dual-accumulator
//      predicated FMA, 8 shared atomics (all R7/R14-proven).

#define BATCH    512
#define NROWS    196
#define KLEN     768
#define IMG_F4   37632           // 3*224*224/4
#define SW2SZ    1584            // 1536 + 1536/32
#define TPB      128
#define PF_F4    1792            // 2 bands ahead, same wn
#define PF_LAST  28              // stop prefetching 28 iters before end

__global__ __launch_bounds__(TPB, 7)
void patch_scorer_kernel(const float* __restrict__ x,
                         const float* __restrict__ W,
                         const float* __restrict__ bias,
                         float* __restrict__ out)
{
    __shared__ float sW2s[SW2SZ];    // sW2s[a + (a>>5)] = W[a % 768], a<1536
    __shared__ float sAcc[100];      // 98 local rows + pad for zero hi-adds

    const int tid   = threadIdx.x;
    const int b     = blockIdx.x >> 1;   // image
    const int ihalf = blockIdx.x & 1;    // patch-row half

    #pragma unroll
    for (int a = tid; a < 2 * KLEN; a += TPB) {
        const int k = (a < KLEN) ? a : a - KLEN;
        sW2s[a + (a >> 5)] = W[k];
    }
    if (tid < 100) sAcc[tid] = 0.0f;
    __syncthreads();

    const int q  = tid >> 5;         // e-quarter 0..3 (warp id)
    const int il = (tid >> 2) & 7;   // local patch row 0..7
    const int jp = tid & 3;          // float4 group (j = 4jp..4jp+3)

    const int tb = il * 16 + jp * 4; // t_local of element m=0
    const int e0 = q * 147;

    const int f0 = tb * 588 + e0;    // local f of element m=0
    const int R0 = f0 / KLEN;        // local rows (0..97)
    const int R1 = (f0 +  588) / KLEN;
    const int R2 = (f0 + 1176) / KLEN;
    const int R3 = (f0 + 1764) / KLEN;
    int a0 = f0          - R0 * KLEN;
    int a1 = (f0 +  588) - R1 * KLEN;
    int a2 = (f0 + 1176) - R2 * KLEN;
    int a3 = (f0 + 1764) - R3 * KLEN;

    const int beta = e0 / 14;        // starting band
    int       wn   = e0 - beta * 14;

    const int i = ihalf * 8 + il;    // global patch row for addressing
    const float4* px = (const float4*)x + (size_t)b * IMG_F4 + i * 56 + jp;
    int off = beta * 896 + wn * 4;   // float4 offset within image

    float l0 = 0.f, h0 = 0.f, l1 = 0.f, h1 = 0.f;
    float l2 = 0.f, h2 = 0.f, l3 = 0.f, h3 = 0.f;

    #pragma unroll 7
    for (int n = 0; n < 147; ++n) {
        if (n < 147 - PF_LAST) {     // L2 prefetch 2 bands ahead (same wn)
            asm volatile("prefetch.global.L2 [%0];"
                         :: "l"(&px[off + PF_F4]));
        }

        const float4 v = __ldcs(&px[off]);

        const float w0 = sW2s[a0 + (a0 >> 5)];
        const float w1 = sW2s[a1 + (a1 >> 5)];
        const float w2 = sW2s[a2 + (a2 >> 5)];
        const float w3 = sW2s[a3 + (a3 >> 5)];

        if (a0 < KLEN) l0 += v.x * w0; else h0 += v.x * w0;
        if (a1 < KLEN) l1 += v.y * w1; else h1 += v.y * w1;
        if (a2 < KLEN) l2 += v.z * w2; else h2 += v.z * w2;
        if (a3 < KLEN) l3 += v.w * w3; else h3 += v.w * w3;

        ++a0; ++a1; ++a2; ++a3;
        off += 4;
        if (++wn == 14) { wn = 0; off += 840; }   // next band
    }

    atomicAdd(&sAcc[R0    ], l0);
    atomicAdd(&sAcc[R0 + 1], h0);
    atomicAdd(&sAcc[R1    ], l1);
    atomicAdd(&sAcc[R1 + 1], h1);
    atomicAdd(&sAcc[R2    ], l2);
    atomicAdd(&sAcc[R2 + 1], h2);
    atomicAdd(&sAcc[R3    ], l3);
    atomicAdd(&sAcc[R3 + 1], h3);

    __syncthreads();

    if (tid < 98)
        out[(size_t)b * NROWS + ihalf * 98 + tid] = sAcc[tid] + bias[0];
}

extern "C" void kernel_launch(void* const* d_in, const int* in_sizes, int n_in,
                              void* d_out, int out_size)
{
    const float* x  = (const float*)d_in[0];   // (512,3,224,224)
    const float* W  = (const float*)d_in[1];   // (1,768)
    const float* bv = (const float*)d_in[2];   // (1,)
    float* out = (float*)d_out;                // (512,196)

    patch_scorer_kernel<<<BATCH * 2, TPB>>>(x, W, bv, out);
}